// round 11
// baseline (speedup 1.0000x reference)
#include <cuda_runtime.h>
#include <cstdint>
#include <math.h>

#define NB     32
#define NH     32
#define NHKV   8
#define NG     4
#define ND     128
#define NPG    32
#define PS     128
#define NPAGES 1024
#define NGRP   (NB * NHKV)             // 256 (b,h) groups, 64 units each
#define NUNITS (NGRP * 64)             // 16384 half-page units, logical order
#define TILE_F 8192                    // floats per half tile (64 x 128)
#define TILE_B 32768u                  // bytes per half tile
#define SCALE  0.08838834764831845f    // 1/sqrt(128)

// -------- device scratch (tiny now: 2 segments per (b,h) group) --------
__device__ float g_m[NGRP * 2 * NG];                       // segment max
__device__ float g_l[NGRP * 2 * NG];                       // segment expsum
__device__ float g_acc[(size_t)NGRP * 2 * NG * ND];        // segment P*V (1 MB)
__device__ unsigned g_arrive;                              // grid-barrier counter
__device__ volatile unsigned g_epoch;                      // grid-barrier epoch

// ---------------- PTX helpers ----------------
__device__ __forceinline__ void mbar_init(uint32_t a, int cnt) {
    asm volatile("mbarrier.init.shared.b64 [%0], %1;" :: "r"(a), "r"(cnt) : "memory");
}
__device__ __forceinline__ void mbar_expect(uint32_t a, uint32_t bytes) {
    asm volatile("mbarrier.arrive.expect_tx.shared.b64 _, [%0], %1;"
                 :: "r"(a), "r"(bytes) : "memory");
}
__device__ __forceinline__ void mbar_wait(uint32_t a, int parity) {
    asm volatile(
        "{\n\t.reg .pred P;\n\t"
        "W%=:\n\t"
        "mbarrier.try_wait.parity.acquire.cta.shared::cta.b64 P, [%0], %1, 0x989680;\n\t"
        "@P bra.uni D%=;\n\t"
        "bra.uni W%=;\n\t"
        "D%=:\n\t}"
        :: "r"(a), "r"(parity) : "memory");
}
__device__ __forceinline__ void bulk_ld(uint32_t dst, const void* src, uint32_t bytes, uint32_t mbar) {
    asm volatile("cp.async.bulk.shared::cta.global.mbarrier::complete_tx::bytes [%0], [%1], %2, [%3];"
                 :: "r"(dst), "l"(src), "r"(bytes), "r"(mbar) : "memory");
}
__device__ __forceinline__ void bulk_st(void* dst, uint32_t src, uint32_t bytes) {
    asm volatile("cp.async.bulk.global.shared::cta.bulk_group [%0], [%1], %2;"
                 :: "l"(dst), "r"(src), "r"(bytes) : "memory");
}

// ---------------------------------------------------------------------------
// Persistent fused update+copy+attend. One block per SM, 512 threads.
// Each block walks a CONTIGUOUS range of units in (b, h, lp, half) order and
// keeps online flash-softmax state in registers/SMEM across a (b,h) group.
// unit u = b*512 + h*64 + lp*2 + hf ; physical page from SMEM page table.
__global__ void __launch_bounds__(512, 1)
fused_kernel(const float* __restrict__ q,
             const float* __restrict__ knew,
             const float* __restrict__ vnew,
             const float* __restrict__ kc,
             const float* __restrict__ vc,
             const int*   __restrict__ pos_,
             const int*   __restrict__ pt,
             float* __restrict__ ok,
             float* __restrict__ ov,
             float* __restrict__ oattn)
{
    extern __shared__ __align__(128) float smf[];
    // layout: K tiles [3][8192] | V tiles [3][8192] | qs[512] | sp[256] |
    //         sml[16] | mbars[8] | spt[1024] | spos[32]
    float* qs  = smf + 6 * TILE_F;
    float* sp  = qs + 512;
    float* sml = sp + 256;                 // m[4], l[4], c0[4]
    const uint32_t smbase = (uint32_t)__cvta_generic_to_shared(smf);
    const uint32_t mb0 = (uint32_t)__cvta_generic_to_shared(sml + 16);
    int* spt  = (int*)(sml + 16 + 8);
    int* spos = spt + NPAGES;

    const int t = threadIdx.x;
    const int w = t >> 5, lane = t & 31;
    const int grid = gridDim.x;
    const int qh = t >> 7, d = t & 127;    // P*V ownership: one (qh,d) per thread

    const unsigned e0 = g_epoch;           // read epoch before own arrival

    const int us = (int)(((long long)blockIdx.x * NUNITS) / grid);
    const int ue = (int)(((long long)(blockIdx.x + 1) * NUNITS) / grid);

    if (t == 0) {
#pragma unroll
        for (int i = 0; i < 3; i++) mbar_init(mb0 + 8 * i, 1);
    }

    // prologue prefetch of unit us (reads pt straight from GMEM)
    if (t == 0) {
        const int b0 = us >> 9, h0 = (us >> 6) & 7, lp0 = (us >> 1) & 31, hf0 = us & 1;
        const int pp0 = __ldg(&pt[b0 * NPG + lp0]);
        const size_t base0 = ((size_t)(pp0 * NHKV + h0)) * 16384 + (size_t)hf0 * 8192;
        mbar_expect(mb0, 2 * TILE_B);
        bulk_ld(smbase,              kc + base0, TILE_B, mb0);
        bulk_ld(smbase + 3 * TILE_B, vc + base0, TILE_B, mb0);
    }

    // SMEM metadata: full page table (4 KB) + positions
    for (int i = t; i < NPAGES; i += 512) spt[i] = pt[i];
    if (t < NB) spos[t] = pos_[t];
    __syncthreads();

    float acc = 0.f;
    int it = 0;
    for (int u = us; u < ue; ++u, ++it) {
        const int s = it % 3, par = (it / 3) & 1;
        float* kb = smf + s * TILE_F;
        float* vb = smf + (3 + s) * TILE_F;

        __syncthreads();   // prev iter's buffer reads + sml/qs uses done

        // ---- prefetch u+1 into stage s+1 (its store group is >=2 groups old) ----
        if (t == 0 && u + 1 < ue) {
            const int un = u + 1;
            const int bn = un >> 9, hn = (un >> 6) & 7, lpn = (un >> 1) & 31, hfn = un & 1;
            const int ppn = spt[bn * NPG + lpn];
            const size_t basen = ((size_t)(ppn * NHKV + hn)) * 16384 + (size_t)hfn * 8192;
            const int sn = (s + 1) % 3;
            asm volatile("cp.async.bulk.wait_group.read 1;" ::: "memory");
            mbar_expect(mb0 + 8 * sn, 2 * TILE_B);
            bulk_ld(smbase + sn * TILE_B,       kc + basen, TILE_B, mb0 + 8 * sn);
            bulk_ld(smbase + (3 + sn) * TILE_B, vc + basen, TILE_B, mb0 + 8 * sn);
        }

        // ---- unit metadata (pure arithmetic + SMEM tables) ----
        const int b = u >> 9, h = (u >> 6) & 7, lp = (u >> 1) & 31, hf = u & 1;
        const int pos = spos[b];
        const int startrow = (lp << 7) + (hf << 6);
        const bool do_attn = startrow <= pos;
        const int nvalid = min(64, pos - startrow + 1);
        const bool has_upd = (lp == (pos >> 7)) && (((pos >> 6) & 1) == hf);
        const int prow = pos & 63;
        const int pp = spt[b * NPG + lp];
        const size_t base = ((size_t)(pp * NHKV + h)) * 16384 + (size_t)hf * 8192;

        // ---- new (b,h) group: reset online-softmax state, load q ----
        if (((u & 63) == 0) || (u == us)) {
            qs[t] = q[((size_t)b * NH + h * NG) * ND + t];
            acc = 0.f;
            if (t < NG) { sml[t] = -INFINITY; sml[NG + t] = 0.f; }
        }

        // ---- wait tiles, patch new token, store back ----
        mbar_wait(mb0 + 8 * s, par);
        if (has_upd) {
            if (t < 32)
                ((float4*)(kb + prow * ND))[t] =
                    ((const float4*)(knew + ((size_t)b * NHKV + h) * ND))[t];
            else if (t < 64)
                ((float4*)(vb + prow * ND))[t - 32] =
                    ((const float4*)(vnew + ((size_t)b * NHKV + h) * ND))[t - 32];
        }
        __syncthreads();

        if (t == 0) {
            asm volatile("fence.proxy.async.shared::cta;" ::: "memory");
            bulk_st(ok + base, smbase + s * TILE_B,       TILE_B);
            bulk_st(ov + base, smbase + (3 + s) * TILE_B, TILE_B);
            asm volatile("cp.async.bulk.commit_group;" ::: "memory");
        }

        if (do_attn) {
            // ---- QK: warp w rows {w, w+16, w+32, w+48}; float4 + shuffle ----
            const float4 q0 = ((const float4*)qs)[lane];
            const float4 q1 = ((const float4*)qs)[32 + lane];
            const float4 q2 = ((const float4*)qs)[64 + lane];
            const float4 q3 = ((const float4*)qs)[96 + lane];
            for (int r = w; r < 64; r += 16) {
                float4 kv = ((const float4*)(kb + r * ND))[lane];
                float s0 = kv.x*q0.x + kv.y*q0.y + kv.z*q0.z + kv.w*q0.w;
                float s1 = kv.x*q1.x + kv.y*q1.y + kv.z*q1.z + kv.w*q1.w;
                float s2 = kv.x*q2.x + kv.y*q2.y + kv.z*q2.z + kv.w*q2.w;
                float s3 = kv.x*q3.x + kv.y*q3.y + kv.z*q3.z + kv.w*q3.w;
#pragma unroll
                for (int off = 16; off; off >>= 1) {
                    s0 += __shfl_xor_sync(0xffffffffu, s0, off);
                    s1 += __shfl_xor_sync(0xffffffffu, s1, off);
                    s2 += __shfl_xor_sync(0xffffffffu, s2, off);
                    s3 += __shfl_xor_sync(0xffffffffu, s3, off);
                }
                if (lane == 0) {
                    bool val = r < nvalid;
                    sp[r]       = val ? s0 * SCALE : -INFINITY;
                    sp[64 + r]  = val ? s1 * SCALE : -INFINITY;
                    sp[128 + r] = val ? s2 * SCALE : -INFINITY;
                    sp[192 + r] = val ? s3 * SCALE : -INFINITY;
                }
            }
            __syncthreads();

            // ---- online softmax update: warp g handles its 64 scores ----
            if (w < NG) {
                float2 v2 = ((const float2*)(sp + w * 64))[lane];
                float mt = fmaxf(v2.x, v2.y);
#pragma unroll
                for (int off = 16; off; off >>= 1)
                    mt = fmaxf(mt, __shfl_xor_sync(0xffffffffu, mt, off));
                const float mold = sml[w];
                const float mnew = fmaxf(mold, mt);
                const float c0 = __expf(mold - mnew);     // -inf -> 0 on first tile
                float ex = __expf(v2.x - mnew), ey = __expf(v2.y - mnew);
                float l = ex + ey;
#pragma unroll
                for (int off = 16; off; off >>= 1)
                    l += __shfl_xor_sync(0xffffffffu, l, off);
                ((float2*)(sp + w * 64))[lane] = make_float2(ex, ey);
                if (lane == 0) {
                    sml[w]          = mnew;
                    sml[NG + w]     = sml[NG + w] * c0 + l;
                    sml[2 * NG + w] = c0;
                }
            }
            __syncthreads();

            // ---- P*V with online rescale: acc = acc*c0 + sum p*v ----
            const float* spq = sp + qh * 64;
            float a = acc * sml[2 * NG + qh];
            int r = 0;
            float a1 = 0.f;
            for (; r + 1 < nvalid; r += 2) {
                a  = fmaf(spq[r],     vb[r * ND + d],       a);
                a1 = fmaf(spq[r + 1], vb[(r + 1) * ND + d], a1);
            }
            if (r < nvalid) a = fmaf(spq[r], vb[r * ND + d], a);
            acc = a + a1;
        }

        // ---- flush at group end (or range end) ----
        if (((u & 63) == 63) || (u == ue - 1)) {
            const int g = u >> 6;
            const int slot = ((g << 6) >= us) ? 0 : 1;
            const int si = (g * 2 + slot) * NG;
            g_acc[(size_t)(si + qh) * ND + d] = acc;
            if (t < NG) { g_m[si + t] = sml[t]; g_l[si + t] = sml[NG + t]; }
            // if the group ends inside our range, nobody writes slot 1 -> mark empty
            if (slot == 0 && ((g << 6) + 63) <= ue - 1 && t < NG) {
                g_m[(g * 2 + 1) * NG + t] = -INFINITY;
                g_l[(g * 2 + 1) * NG + t] = 0.f;
            }
            acc = 0.f;
        }
    }

    // drain outstanding bulk stores (SMEM safety + GMEM visibility)
    if (t == 0) asm volatile("cp.async.bulk.wait_group 0;" ::: "memory");

    // ================= grid-wide barrier (all blocks co-resident) =============
    __threadfence();                       // publish segment partials
    __syncthreads();
    if (t == 0) {
        unsigned n = atomicAdd(&g_arrive, 1u);
        if (n == (unsigned)grid - 1u) {
            g_arrive = 0;                  // reset for next graph replay
            __threadfence();
            g_epoch = e0 + 1u;             // release
        }
        while (g_epoch == e0) { }          // spin (volatile read)
    }
    __syncthreads();
    __threadfence();                       // acquire partials from all blocks

    // ================= final combine: at most 2 segments per head =============
    const int tot = NB * NH * ND;          // 131072
    for (int idx = blockIdx.x * 512 + t; idx < tot; idx += grid * 512) {
        const int uu = idx >> 7, dd = idx & 127;
        const int qq = uu & 3;                               // qh within group
        const int g  = (uu >> 5) * NHKV + ((uu >> 2) & 7);   // b*8 + h
        const int i0 = (g * 2) * NG + qq;
        const int i1 = (g * 2 + 1) * NG + qq;
        const float m0 = g_m[i0], m1 = g_m[i1];
        const float M  = fmaxf(m0, m1);                      // m0 always finite
        const float c0 = __expf(m0 - M);
        const float c1 = __expf(m1 - M);                     // 0 if segment empty
        const float O = g_acc[(size_t)i0 * ND + dd] * c0 +
                        g_acc[(size_t)i1 * ND + dd] * c1;
        const float L = g_l[i0] * c0 + g_l[i1] * c1;
        oattn[idx] = O / L;
    }
}

// ---------------------------------------------------------------------------
extern "C" void kernel_launch(void* const* d_in, const int* in_sizes, int n_in,
                              void* d_out, int out_size)
{
    const float* q   = (const float*)d_in[0];
    const float* kn  = (const float*)d_in[1];
    const float* vn  = (const float*)d_in[2];
    const float* kc  = (const float*)d_in[3];
    const float* vc  = (const float*)d_in[4];
    const int*   pos = (const int*)d_in[5];
    const int*   pt  = (const int*)d_in[6];

    float* out_attn = (float*)d_out;
    float* out_k    = out_attn + (size_t)NB * NH * ND;             // +131072
    float* out_v    = out_k + (size_t)NPAGES * NHKV * PS * ND;     // +134217728

    int nsm = 148;
    if (cudaDeviceGetAttribute(&nsm, cudaDevAttrMultiProcessorCount, 0) != cudaSuccess || nsm <= 0)
        nsm = 148;

    // 6 tiles*32KB + qs 2KB + sp 1KB + sml 64B + mbars 32B + spt 4KB + spos 128B
    const int smem = (6 * TILE_F + 512 + 256 + 16 + 8 + 1024 + 32) * (int)sizeof(float);
    cudaFuncSetAttribute(fused_kernel, cudaFuncAttributeMaxDynamicSharedMemorySize, smem);

    fused_kernel<<<nsm, 512, smem>>>(q, kn, vn, kc, vc, pos, pt,
                                     out_k, out_v, out_attn);
}

// round 12
// speedup vs baseline: 1.0439x; 1.0439x over previous
#include <cuda_runtime.h>
#include <cstdint>
#include <math.h>

#define NB     32
#define NH     32
#define NHKV   8
#define NG     4
#define ND     128
#define NPG    32
#define PS     128
#define NPAGES 1024
#define NPAIR  16384                   // 64-row half-page pairs (physical order)
#define NHP    64                      // partials per (b,qhead): lp*2+hf
#define STEP_F 4096                    // floats per 32-row step tile
#define STEP_B 16384u                  // bytes per step tile
#define SCALE  0.08838834764831845f    // 1/sqrt(128)

// -------- device scratch (static: allocation-free) --------
__device__ float g_Pm[NB * NH * NHP];                           // partial max
__device__ float g_Pl[NB * NH * NHP];                           // partial expsum
__device__ float g_Pacc[(size_t)NB * NH * NHP * ND];            // partial P*V (33.5 MB)
__device__ unsigned g_arrive;                                   // grid-barrier counter
__device__ volatile unsigned g_epoch;                           // grid-barrier epoch

// ---------------- PTX helpers ----------------
__device__ __forceinline__ void mbar_init(uint32_t a, int cnt) {
    asm volatile("mbarrier.init.shared.b64 [%0], %1;" :: "r"(a), "r"(cnt) : "memory");
}
__device__ __forceinline__ void mbar_expect(uint32_t a, uint32_t bytes) {
    asm volatile("mbarrier.arrive.expect_tx.shared.b64 _, [%0], %1;"
                 :: "r"(a), "r"(bytes) : "memory");
}
__device__ __forceinline__ void mbar_wait(uint32_t a, int parity) {
    asm volatile(
        "{\n\t.reg .pred P;\n\t"
        "W%=:\n\t"
        "mbarrier.try_wait.parity.acquire.cta.shared::cta.b64 P, [%0], %1, 0x989680;\n\t"
        "@P bra.uni D%=;\n\t"
        "bra.uni W%=;\n\t"
        "D%=:\n\t}"
        :: "r"(a), "r"(parity) : "memory");
}
__device__ __forceinline__ void bulk_ld(uint32_t dst, const void* src, uint32_t bytes, uint32_t mbar) {
    asm volatile("cp.async.bulk.shared::cta.global.mbarrier::complete_tx::bytes [%0], [%1], %2, [%3];"
                 :: "r"(dst), "l"(src), "r"(bytes), "r"(mbar) : "memory");
}
__device__ __forceinline__ void bulk_st(void* dst, uint32_t src, uint32_t bytes) {
    asm volatile("cp.async.bulk.global.shared::cta.bulk_group [%0], [%1], %2;"
                 :: "l"(dst), "r"(src), "r"(bytes) : "memory");
}

// ---------------------------------------------------------------------------
// Persistent fused update+copy+attend+reduce. TWO blocks per SM, 512 threads.
// Blocks walk 64-row pairs in PHYSICAL order (strided by grid); each pair is
// processed as two 32-row pipeline steps with a 2-step online softmax, then
// flushed as one split-softmax partial (same layout as before).
__global__ void __launch_bounds__(512, 2)
fused_kernel(const float* __restrict__ q,
             const float* __restrict__ knew,
             const float* __restrict__ vnew,
             const float* __restrict__ kc,
             const float* __restrict__ vc,
             const int*   __restrict__ pos_,
             const int*   __restrict__ pt,
             float* __restrict__ ok,
             float* __restrict__ ov,
             float* __restrict__ oattn)
{
    extern __shared__ __align__(128) float smf[];
    // layout (floats): K steps [3][4096] | V steps [3][4096] | qs[512] |
    //                  sp[128] | sml[16] | mbars[8] | sinv[1024] | spos[32] | supd[32]
    float* qs  = smf + 6 * STEP_F;         // 24576
    float* sp  = qs + 512;                 // 25088
    float* sml = sp + 128;                 // m[4], l[4], c0[4]
    const uint32_t smbase = (uint32_t)__cvta_generic_to_shared(smf);
    const uint32_t mb0 = (uint32_t)__cvta_generic_to_shared(sml + 16);
    int* sinv = (int*)(sml + 16 + 8);
    int* spos = sinv + NPAGES;
    int* supd = spos + 32;

    const int t = threadIdx.x;
    const int w = t >> 5, lane = t & 31;
    const int grid = gridDim.x;
    const int qh = t >> 7, d = t & 127;    // P*V ownership: one (qh,d) per thread

    const unsigned e0 = g_epoch;           // read epoch before own arrival

    if (t == 0) {
#pragma unroll
        for (int i = 0; i < 3; i++) mbar_init(mb0 + 8 * i, 1);
    }

    // prologue prefetch: first step of first pair
    if (t == 0 && blockIdx.x < NPAIR) {
        const size_t b0 = (size_t)blockIdx.x * 8192;
        mbar_expect(mb0, 2 * STEP_B);
        bulk_ld(smbase,              kc + b0, STEP_B, mb0);
        bulk_ld(smbase + 3 * STEP_B, vc + b0, STEP_B, mb0);
    }

    // SMEM metadata: inverse page table + positions + update page
    for (int i = t; i < NPAGES; i += 512) sinv[pt[i]] = i;
    if (t < NB) {
        int p = pos_[t];
        spos[t] = p;
        supd[t] = pt[t * NPG + (p >> 7)];
    }
    __syncthreads();

    float acc = 0.f;
    int it = 0;
    for (int pair = blockIdx.x; pair < NPAIR; pair += grid) {
        // per-pair metadata
        const int pp = pair >> 4, h = (pair >> 1) & 7, hf = pair & 1;
        const int owner = sinv[pp];
        const int b = owner >> 5, lp = owner & 31;
        const int pos = spos[b];
        const int pairrow = (lp << 7) + (hf << 6);
        const bool pair_attn = pairrow <= pos;
        const size_t pbase = (size_t)pair * 8192;

#pragma unroll
        for (int sub = 0; sub < 2; ++sub, ++it) {
            const int s = it % 3, par = (it / 3) & 1;
            float* kb = smf + s * STEP_F;
            float* vb = smf + (3 + s) * STEP_F;

            __syncthreads();   // prev step's buffer reads / sml uses done

            // ---- prefetch next step into stage s+1 ----
            if (t == 0) {
                int npair = pair, nsub = sub + 1;
                if (nsub == 2) { npair = pair + grid; nsub = 0; }
                if (npair < NPAIR) {
                    const int sn = (s + 1) % 3;
                    asm volatile("cp.async.bulk.wait_group.read 1;" ::: "memory");
                    mbar_expect(mb0 + 8 * sn, 2 * STEP_B);
                    const size_t nb = (size_t)npair * 8192 + (size_t)nsub * STEP_F;
                    bulk_ld(smbase + sn * STEP_B,       kc + nb, STEP_B, mb0 + 8 * sn);
                    bulk_ld(smbase + (3 + sn) * STEP_B, vc + nb, STEP_B, mb0 + 8 * sn);
                }
            }

            const int startrow = pairrow + (sub << 5);
            const bool do_attn = startrow <= pos;
            const int nvalid = min(32, pos - startrow + 1);
            const bool has_upd = (pp == supd[b]) && (((pos >> 5) & 3) == ((hf << 1) | sub));
            const int prow = pos & 31;
            const size_t base = pbase + (size_t)sub * STEP_F;

            if (sub == 0) {
                acc = 0.f;
                if (do_attn) qs[t] = q[((size_t)b * NH + h * NG) * ND + t];
                if (t < 8) sml[t] = (t < 4) ? -INFINITY : 0.f;   // m=-inf, l=0
            }

            // ---- wait tile, patch new token, store back ----
            mbar_wait(mb0 + 8 * s, par);
            if (has_upd) {
                if (t < 32)
                    ((float4*)(kb + prow * ND))[t] =
                        ((const float4*)(knew + ((size_t)b * NHKV + h) * ND))[t];
                else if (t < 64)
                    ((float4*)(vb + prow * ND))[t - 32] =
                        ((const float4*)(vnew + ((size_t)b * NHKV + h) * ND))[t - 32];
            }
            __syncthreads();

            if (t == 0) {
                asm volatile("fence.proxy.async.shared::cta;" ::: "memory");
                bulk_st(ok + base, smbase + s * STEP_B,       STEP_B);
                bulk_st(ov + base, smbase + (3 + s) * STEP_B, STEP_B);
                asm volatile("cp.async.bulk.commit_group;" ::: "memory");
            }

            if (do_attn) {
                // ---- QK: warp w rows {w, w+16}; float4 + shuffle ----
                const float4 q0 = ((const float4*)qs)[lane];
                const float4 q1 = ((const float4*)qs)[32 + lane];
                const float4 q2 = ((const float4*)qs)[64 + lane];
                const float4 q3 = ((const float4*)qs)[96 + lane];
#pragma unroll
                for (int r = w; r < 32; r += 16) {
                    float4 kv = ((const float4*)(kb + r * ND))[lane];
                    float s0 = kv.x*q0.x + kv.y*q0.y + kv.z*q0.z + kv.w*q0.w;
                    float s1 = kv.x*q1.x + kv.y*q1.y + kv.z*q1.z + kv.w*q1.w;
                    float s2 = kv.x*q2.x + kv.y*q2.y + kv.z*q2.z + kv.w*q2.w;
                    float s3 = kv.x*q3.x + kv.y*q3.y + kv.z*q3.z + kv.w*q3.w;
#pragma unroll
                    for (int off = 16; off; off >>= 1) {
                        s0 += __shfl_xor_sync(0xffffffffu, s0, off);
                        s1 += __shfl_xor_sync(0xffffffffu, s1, off);
                        s2 += __shfl_xor_sync(0xffffffffu, s2, off);
                        s3 += __shfl_xor_sync(0xffffffffu, s3, off);
                    }
                    if (lane == 0) {
                        bool val = r < nvalid;
                        sp[r]      = val ? s0 * SCALE : -INFINITY;
                        sp[32 + r] = val ? s1 * SCALE : -INFINITY;
                        sp[64 + r] = val ? s2 * SCALE : -INFINITY;
                        sp[96 + r] = val ? s3 * SCALE : -INFINITY;
                    }
                }
                __syncthreads();

                // ---- online softmax update: warp g over its 32 scores ----
                if (w < NG) {
                    float x = sp[w * 32 + lane];
                    float mt = x;
#pragma unroll
                    for (int off = 16; off; off >>= 1)
                        mt = fmaxf(mt, __shfl_xor_sync(0xffffffffu, mt, off));
                    const float mold = sml[w];
                    const float mnew = fmaxf(mold, mt);
                    const float c0 = __expf(mold - mnew);    // 0 on first step
                    float e = __expf(x - mnew);
                    float l = e;
#pragma unroll
                    for (int off = 16; off; off >>= 1)
                        l += __shfl_xor_sync(0xffffffffu, l, off);
                    sp[w * 32 + lane] = e;
                    if (lane == 0) {
                        sml[w]     = mnew;
                        sml[4 + w] = sml[4 + w] * c0 + l;
                        sml[8 + w] = c0;
                    }
                }
                __syncthreads();

                // ---- P*V with online rescale ----
                const float* spq = sp + qh * 32;
                float a = acc * sml[8 + qh];
                float a1 = 0.f;
                int r = 0;
                for (; r + 1 < nvalid; r += 2) {
                    a  = fmaf(spq[r],     vb[r * ND + d],       a);
                    a1 = fmaf(spq[r + 1], vb[(r + 1) * ND + d], a1);
                }
                if (r < nvalid) a = fmaf(spq[r], vb[r * ND + d], a);
                acc = a + a1;
            }

            // ---- flush the pair's partial at end of second step ----
            if (sub == 1 && pair_attn) {
                const int u0 = b * NH + h * NG;
                g_Pacc[(size_t)((u0 + qh) * NHP + lp * 2 + hf) * ND + d] = acc;
                if (t < NG) {
                    const int id = (u0 + t) * NHP + lp * 2 + hf;
                    g_Pm[id] = sml[t];
                    g_Pl[id] = sml[4 + t];
                }
            }
        }
    }

    // drain outstanding bulk stores (SMEM safety + GMEM visibility)
    if (t == 0) asm volatile("cp.async.bulk.wait_group 0;" ::: "memory");

    // ================= grid-wide barrier (all 2*SM blocks co-resident) ========
    __threadfence();                       // publish partials
    __syncthreads();
    if (t == 0) {
        unsigned n = atomicAdd(&g_arrive, 1u);
        if (n == (unsigned)grid - 1u) {
            g_arrive = 0;                  // reset for next graph replay
            __threadfence();
            g_epoch = e0 + 1u;             // release
        }
        while (g_epoch == e0) { }          // spin (volatile read)
    }
    __syncthreads();
    __threadfence();                       // acquire partials from all blocks

    // ================= softmax combine (two-pass, one expf per partial) =======
    const int tot = NB * NH * ND;          // 131072 work items
    for (int idx = blockIdx.x * 512 + t; idx < tot; idx += grid * 512) {
        const int uu = idx >> 7, dd = idx & 127;
        const int b = uu >> 5;
        const int nhp = (spos[b] >> 6) + 1;

        float M = -INFINITY;
        for (int hp = 0; hp < nhp; hp++)
            M = fmaxf(M, g_Pm[uu * NHP + hp]);

        float L = 0.f, O = 0.f;
        for (int hp = 0; hp < nhp; hp++) {
            float c = __expf(g_Pm[uu * NHP + hp] - M);
            O = fmaf(g_Pacc[(size_t)(uu * NHP + hp) * ND + dd], c, O);
            L = fmaf(g_Pl[uu * NHP + hp], c, L);
        }
        oattn[idx] = O / L;
    }
}

// ---------------------------------------------------------------------------
extern "C" void kernel_launch(void* const* d_in, const int* in_sizes, int n_in,
                              void* d_out, int out_size)
{
    const float* q   = (const float*)d_in[0];
    const float* kn  = (const float*)d_in[1];
    const float* vn  = (const float*)d_in[2];
    const float* kc  = (const float*)d_in[3];
    const float* vc  = (const float*)d_in[4];
    const int*   pos = (const int*)d_in[5];
    const int*   pt  = (const int*)d_in[6];

    float* out_attn = (float*)d_out;
    float* out_k    = out_attn + (size_t)NB * NH * ND;             // +131072
    float* out_v    = out_k + (size_t)NPAGES * NHKV * PS * ND;     // +134217728

    int nsm = 148;
    if (cudaDeviceGetAttribute(&nsm, cudaDevAttrMultiProcessorCount, 0) != cudaSuccess || nsm <= 0)
        nsm = 148;

    // 6 steps*16KB + qs 2KB + sp 512B + sml 64B + mbars 32B + sinv 4KB + 256B
    const int smem = (6 * STEP_F + 512 + 128 + 16 + 8 + 1024 + 64) * (int)sizeof(float); // ~105 KB
    cudaFuncSetAttribute(fused_kernel, cudaFuncAttributeMaxDynamicSharedMemorySize, smem);

    fused_kernel<<<2 * nsm, 512, smem>>>(q, kn, vn, kc, vc, pos, pt,
                                         out_k, out_v, out_attn);
}

// round 13
// speedup vs baseline: 1.0790x; 1.0336x over previous
#include <cuda_runtime.h>
#include <cstdint>
#include <math.h>

#define NB     32
#define NH     32
#define NHKV   8
#define NG     4
#define ND     128
#define NPG    32
#define PS     128
#define NPAGES 1024
#define NPAIRS (NPAGES * NHKV)         // 8192 (page,head) pairs, physical order
#define NHP    32                      // one partial per logical page now
#define TILE_F 8192                    // floats per 64-row step tile (32 KB)
#define TILE_B 32768u
#define SCALE  0.08838834764831845f    // 1/sqrt(128)

// -------- device scratch (static: allocation-free) --------
__device__ float g_Pm[NB * NH * NHP];                           // partial max
__device__ float g_Pl[NB * NH * NHP];                           // partial expsum
__device__ float g_Pacc[(size_t)NB * NH * NHP * ND];            // partial P*V (16.7 MB)

// ---------------- PTX helpers ----------------
__device__ __forceinline__ void mbar_init(uint32_t a, int cnt) {
    asm volatile("mbarrier.init.shared.b64 [%0], %1;" :: "r"(a), "r"(cnt) : "memory");
}
__device__ __forceinline__ void mbar_expect(uint32_t a, uint32_t bytes) {
    asm volatile("mbarrier.arrive.expect_tx.shared.b64 _, [%0], %1;"
                 :: "r"(a), "r"(bytes) : "memory");
}
__device__ __forceinline__ void mbar_wait(uint32_t a, int parity) {
    asm volatile(
        "{\n\t.reg .pred P;\n\t"
        "W%=:\n\t"
        "mbarrier.try_wait.parity.acquire.cta.shared::cta.b64 P, [%0], %1, 0x989680;\n\t"
        "@P bra.uni D%=;\n\t"
        "bra.uni W%=;\n\t"
        "D%=:\n\t}"
        :: "r"(a), "r"(parity) : "memory");
}
__device__ __forceinline__ void bulk_ld(uint32_t dst, const void* src, uint32_t bytes, uint32_t mbar) {
    asm volatile("cp.async.bulk.shared::cta.global.mbarrier::complete_tx::bytes [%0], [%1], %2, [%3];"
                 :: "r"(dst), "l"(src), "r"(bytes), "r"(mbar) : "memory");
}
__device__ __forceinline__ void bulk_st(void* dst, uint32_t src, uint32_t bytes) {
    asm volatile("cp.async.bulk.global.shared::cta.bulk_group [%0], [%1], %2;"
                 :: "l"(dst), "r"(src), "r"(bytes) : "memory");
}

// ---------------------------------------------------------------------------
// Persistent fused copy+update+attend. One block per SM, 512 threads.
// Blocks stride over (page,head) PAIRS in physical order; each pair is two
// consecutive 64-row pipeline steps (identical streaming shape to the best
// kernel) merged by a 2-step online softmax -> one partial per logical page.
__global__ void __launch_bounds__(512, 1)
fused_kernel(const float* __restrict__ q,
             const float* __restrict__ knew,
             const float* __restrict__ vnew,
             const float* __restrict__ kc,
             const float* __restrict__ vc,
             const int*   __restrict__ pos_,
             const int*   __restrict__ pt,
             float* __restrict__ ok,
             float* __restrict__ ov)
{
    extern __shared__ __align__(128) float smf[];
    // layout: K steps [3][8192] | V steps [3][8192] | qs[512] | sp[256] |
    //         sml[16] | mbars[8] | sinv[1024] | spos[32] | supd[32]
    float* qs  = smf + 6 * TILE_F;
    float* sp  = qs + 512;
    float* sml = sp + 256;                 // m[4], l[4], c0[4]
    const uint32_t smbase = (uint32_t)__cvta_generic_to_shared(smf);
    const uint32_t mb0 = (uint32_t)__cvta_generic_to_shared(sml + 16);
    int* sinv = (int*)(sml + 16 + 8);
    int* spos = sinv + NPAGES;
    int* supd = spos + 32;

    const int t = threadIdx.x;
    const int w = t >> 5, lane = t & 31;
    const int grid = gridDim.x;
    const int qh = t >> 7, d = t & 127;    // P*V ownership: one (qh,d) per thread

    if (t == 0) {
#pragma unroll
        for (int i = 0; i < 3; i++) mbar_init(mb0 + 8 * i, 1);
    }

    // prologue prefetch: first step (hf=0) of first pair — pure physical address
    if (t == 0 && blockIdx.x < NPAIRS) {
        const size_t b0 = (size_t)blockIdx.x * 16384;
        mbar_expect(mb0, 2 * TILE_B);
        bulk_ld(smbase,              kc + b0, TILE_B, mb0);
        bulk_ld(smbase + 3 * TILE_B, vc + b0, TILE_B, mb0);
    }

    // SMEM metadata: inverse page table + positions + update page
    for (int i = t; i < NPAGES; i += 512) sinv[pt[i]] = i;
    if (t < NB) {
        int p = pos_[t];
        spos[t] = p;
        supd[t] = pt[t * NPG + (p >> 7)];
    }
    __syncthreads();

    float acc = 0.f;
    int it = 0;
    for (int p = blockIdx.x; p < NPAIRS; p += grid) {
        const int pp = p >> 3, h = p & 7;
        const int owner = sinv[pp];
        const int b = owner >> 5, lp = owner & 31;
        const int pos = spos[b];
        const bool pair_attn = (lp << 7) <= pos;

#pragma unroll
        for (int hf = 0; hf < 2; ++hf, ++it) {
            const int s = it % 3, par = (it / 3) & 1;
            float* kb = smf + s * TILE_F;
            float* vb = smf + (3 + s) * TILE_F;

            __syncthreads();   // prev step's buffer reads / sml-qs uses done

            // ---- prefetch next step into stage s+1 ----
            if (t == 0) {
                int np = p, nhf = hf + 1;
                if (nhf == 2) { np = p + grid; nhf = 0; }
                if (np < NPAIRS) {
                    const int sn = (s + 1) % 3;
                    asm volatile("cp.async.bulk.wait_group.read 1;" ::: "memory");
                    mbar_expect(mb0 + 8 * sn, 2 * TILE_B);
                    const size_t nb = (size_t)np * 16384 + (size_t)nhf * TILE_F;
                    bulk_ld(smbase + sn * TILE_B,       kc + nb, TILE_B, mb0 + 8 * sn);
                    bulk_ld(smbase + (3 + sn) * TILE_B, vc + nb, TILE_B, mb0 + 8 * sn);
                }
            }

            const int startrow = (lp << 7) + (hf << 6);
            const bool do_attn = startrow <= pos;
            const int nvalid = min(64, pos - startrow + 1);
            const bool has_upd = (pp == supd[b]) && (((pos >> 6) & 1) == hf);
            const int prow = pos & 63;
            const size_t base = (size_t)p * 16384 + (size_t)hf * TILE_F;

            if (hf == 0) {
                acc = 0.f;
                if (pair_attn) qs[t] = q[((size_t)b * NH + h * NG) * ND + t];
                if (t < 8) sml[t] = (t < 4) ? -INFINITY : 0.f;   // m=-inf, l=0
            }

            // ---- wait tile, patch new token, store back ----
            mbar_wait(mb0 + 8 * s, par);
            if (has_upd) {
                if (t < 32)
                    ((float4*)(kb + prow * ND))[t] =
                        ((const float4*)(knew + ((size_t)b * NHKV + h) * ND))[t];
                else if (t < 64)
                    ((float4*)(vb + prow * ND))[t - 32] =
                        ((const float4*)(vnew + ((size_t)b * NHKV + h) * ND))[t - 32];
            }
            __syncthreads();

            if (t == 0) {
                asm volatile("fence.proxy.async.shared::cta;" ::: "memory");
                bulk_st(ok + base, smbase + s * TILE_B,       TILE_B);
                bulk_st(ov + base, smbase + (3 + s) * TILE_B, TILE_B);
                asm volatile("cp.async.bulk.commit_group;" ::: "memory");
            }

            if (do_attn) {
                // ---- QK: warp w rows {w, w+16, w+32, w+48}; float4 + shuffle ----
                const float4 q0 = ((const float4*)qs)[lane];
                const float4 q1 = ((const float4*)qs)[32 + lane];
                const float4 q2 = ((const float4*)qs)[64 + lane];
                const float4 q3 = ((const float4*)qs)[96 + lane];
                for (int r = w; r < 64; r += 16) {
                    float4 kv = ((const float4*)(kb + r * ND))[lane];
                    float s0 = kv.x*q0.x + kv.y*q0.y + kv.z*q0.z + kv.w*q0.w;
                    float s1 = kv.x*q1.x + kv.y*q1.y + kv.z*q1.z + kv.w*q1.w;
                    float s2 = kv.x*q2.x + kv.y*q2.y + kv.z*q2.z + kv.w*q2.w;
                    float s3 = kv.x*q3.x + kv.y*q3.y + kv.z*q3.z + kv.w*q3.w;
#pragma unroll
                    for (int off = 16; off; off >>= 1) {
                        s0 += __shfl_xor_sync(0xffffffffu, s0, off);
                        s1 += __shfl_xor_sync(0xffffffffu, s1, off);
                        s2 += __shfl_xor_sync(0xffffffffu, s2, off);
                        s3 += __shfl_xor_sync(0xffffffffu, s3, off);
                    }
                    if (lane == 0) {
                        bool val = r < nvalid;
                        sp[r]       = val ? s0 * SCALE : -INFINITY;
                        sp[64 + r]  = val ? s1 * SCALE : -INFINITY;
                        sp[128 + r] = val ? s2 * SCALE : -INFINITY;
                        sp[192 + r] = val ? s3 * SCALE : -INFINITY;
                    }
                }
                __syncthreads();

                // ---- online softmax update: warp g over its 64 scores ----
                if (w < NG) {
                    float2 v2 = ((const float2*)(sp + w * 64))[lane];
                    float mt = fmaxf(v2.x, v2.y);
#pragma unroll
                    for (int off = 16; off; off >>= 1)
                        mt = fmaxf(mt, __shfl_xor_sync(0xffffffffu, mt, off));
                    const float mold = sml[w];
                    const float mnew = fmaxf(mold, mt);
                    const float c0 = __expf(mold - mnew);    // 0 on first step
                    float ex = __expf(v2.x - mnew), ey = __expf(v2.y - mnew);
                    float l = ex + ey;
#pragma unroll
                    for (int off = 16; off; off >>= 1)
                        l += __shfl_xor_sync(0xffffffffu, l, off);
                    ((float2*)(sp + w * 64))[lane] = make_float2(ex, ey);
                    if (lane == 0) {
                        sml[w]     = mnew;
                        sml[4 + w] = sml[4 + w] * c0 + l;
                        sml[8 + w] = c0;
                    }
                }
                __syncthreads();

                // ---- P*V with online rescale: acc = acc*c0 + sum p*v ----
                const float* spq = sp + qh * 64;
                float a = acc * sml[8 + qh];
                float a1 = 0.f;
                int r = 0;
                for (; r + 1 < nvalid; r += 2) {
                    a  = fmaf(spq[r],     vb[r * ND + d],       a);
                    a1 = fmaf(spq[r + 1], vb[(r + 1) * ND + d], a1);
                }
                if (r < nvalid) a = fmaf(spq[r], vb[r * ND + d], a);
                acc = a + a1;
            }
        }

        // ---- flush one partial per (pair, qhead) at logical page lp ----
        if (pair_attn) {
            const int u0 = b * NH + h * NG;
            g_Pacc[(size_t)((u0 + qh) * NHP + lp) * ND + d] = acc;
            if (t < NG) {
                const int id = (u0 + t) * NHP + lp;
                g_Pm[id] = sml[t];
                g_Pl[id] = sml[4 + t];
            }
        }
    }

    // drain outstanding bulk stores (SMEM safety + GMEM visibility)
    if (t == 0) asm volatile("cp.async.bulk.wait_group 0;" ::: "memory");
}

// ---------------------------------------------------------------------------
// Combine split-softmax partials: one block per (b, q-head), 128 threads.
__global__ void reduce_kernel(const int* __restrict__ pos_, float* __restrict__ out)
{
    const int uu = blockIdx.x;             // b*32 + h*4 + g
    const int b = uu >> 5;
    const int dd = threadIdx.x;
    const int npg = (pos_[b] >> 7) + 1;

    float M = -INFINITY;
    for (int lp = 0; lp < npg; lp++)
        M = fmaxf(M, g_Pm[uu * NHP + lp]);

    float L = 0.f, O = 0.f;
    for (int lp = 0; lp < npg; lp++) {
        float c = __expf(g_Pm[uu * NHP + lp] - M);
        O = fmaf(g_Pacc[(size_t)(uu * NHP + lp) * ND + dd], c, O);
        L = fmaf(g_Pl[uu * NHP + lp], c, L);
    }
    out[(size_t)uu * ND + dd] = O / L;
}

// ---------------------------------------------------------------------------
extern "C" void kernel_launch(void* const* d_in, const int* in_sizes, int n_in,
                              void* d_out, int out_size)
{
    const float* q   = (const float*)d_in[0];
    const float* kn  = (const float*)d_in[1];
    const float* vn  = (const float*)d_in[2];
    const float* kc  = (const float*)d_in[3];
    const float* vc  = (const float*)d_in[4];
    const int*   pos = (const int*)d_in[5];
    const int*   pt  = (const int*)d_in[6];

    float* out_attn = (float*)d_out;
    float* out_k    = out_attn + (size_t)NB * NH * ND;             // +131072
    float* out_v    = out_k + (size_t)NPAGES * NHKV * PS * ND;     // +134217728

    int nsm = 148;
    if (cudaDeviceGetAttribute(&nsm, cudaDevAttrMultiProcessorCount, 0) != cudaSuccess || nsm <= 0)
        nsm = 148;

    // 6 tiles*32KB + qs 2KB + sp 1KB + sml 64B + mbars 32B + sinv 4KB + 256B
    const int smem = (6 * TILE_F + 512 + 256 + 16 + 8 + 1024 + 64) * (int)sizeof(float); // ~204 KB
    cudaFuncSetAttribute(fused_kernel, cudaFuncAttributeMaxDynamicSharedMemorySize, smem);

    fused_kernel<<<nsm, 512, smem>>>(q, kn, vn, kc, vc, pos, pt, out_k, out_v);
    reduce_kernel<<<NB * NH, ND>>>(pos, out_attn);
}

// round 14
// speedup vs baseline: 1.1391x; 1.0557x over previous
#include <cuda_runtime.h>
#include <cstdint>
#include <math.h>

#define NB     32
#define NH     32
#define NHKV   8
#define NG     4
#define ND     128
#define NPG    32
#define PS     128
#define NPAGES 1024
#define NUNITS (NPAGES * NHKV * 2)     // 16384 half-page units, physical order
#define NHP    64                      // partials per (b,qhead): lp*2+hf
#define TILE_F 8192                    // floats per half tile (64 x 128)
#define TILE_B 32768u
#define SCALE  0.08838834764831845f    // 1/sqrt(128)

// -------- device scratch (static: allocation-free) --------
__device__ float g_Pm[NB * NH * NHP];                           // partial max
__device__ float g_Pl[NB * NH * NHP];                           // partial expsum
__device__ float g_Pacc[(size_t)NB * NH * NHP * ND];            // partial P*V (33.5 MB)

// ---------------- PTX helpers ----------------
__device__ __forceinline__ void mbar_init(uint32_t a, int cnt) {
    asm volatile("mbarrier.init.shared.b64 [%0], %1;" :: "r"(a), "r"(cnt) : "memory");
}
__device__ __forceinline__ void mbar_expect(uint32_t a, uint32_t bytes) {
    asm volatile("mbarrier.arrive.expect_tx.shared.b64 _, [%0], %1;"
                 :: "r"(a), "r"(bytes) : "memory");
}
__device__ __forceinline__ void mbar_wait(uint32_t a, int parity) {
    asm volatile(
        "{\n\t.reg .pred P;\n\t"
        "W%=:\n\t"
        "mbarrier.try_wait.parity.acquire.cta.shared::cta.b64 P, [%0], %1, 0x989680;\n\t"
        "@P bra.uni D%=;\n\t"
        "bra.uni W%=;\n\t"
        "D%=:\n\t}"
        :: "r"(a), "r"(parity) : "memory");
}
__device__ __forceinline__ void bulk_ld(uint32_t dst, const void* src, uint32_t bytes, uint32_t mbar) {
    asm volatile("cp.async.bulk.shared::cta.global.mbarrier::complete_tx::bytes [%0], [%1], %2, [%3];"
                 :: "r"(dst), "l"(src), "r"(bytes), "r"(mbar) : "memory");
}
__device__ __forceinline__ void bulk_st(void* dst, uint32_t src, uint32_t bytes) {
    asm volatile("cp.async.bulk.global.shared::cta.bulk_group [%0], [%1], %2;"
                 :: "l"(dst), "r"(src), "r"(bytes) : "memory");
}

// ---------------------------------------------------------------------------
// Persistent fused update+copy+attend (R9's proven 336us hot loop, verbatim:
// strided physical-order units, 64KB steps, per-unit split-softmax partials).
__global__ void __launch_bounds__(512, 1)
fused_kernel(const float* __restrict__ q,
             const float* __restrict__ knew,
             const float* __restrict__ vnew,
             const float* __restrict__ kc,
             const float* __restrict__ vc,
             const int*   __restrict__ pos_,
             const int*   __restrict__ pt,
             float* __restrict__ ok,
             float* __restrict__ ov)
{
    extern __shared__ __align__(128) float smf[];
    // layout: K tiles [3][8192] | V tiles [3][8192] | qs[512] | sp[256] |
    //         mbars(16f) | sinv[1024] | spos[32] | supd[32]
    float* qs = smf + 6 * TILE_F;
    float* sp = qs + 512;
    const uint32_t smbase = (uint32_t)__cvta_generic_to_shared(smf);
    const uint32_t mb0 = (uint32_t)__cvta_generic_to_shared(sp + 256);
    int*  sinv = (int*)(sp + 256 + 16);
    int*  spos = sinv + 1024;
    int*  supd = spos + 32;

    const int t = threadIdx.x;
    const int w = t >> 5, lane = t & 31;
    const int grid = gridDim.x;

    if (t == 0) {
#pragma unroll
        for (int i = 0; i < 3; i++) mbar_init(mb0 + 8 * i, 1);
    }

    int u = blockIdx.x;
    // prologue prefetch (pure physical address, needs no metadata)
    if (t == 0 && u < NUNITS) {
        mbar_expect(mb0, 2 * TILE_B);
        bulk_ld(smbase,              kc + (size_t)u * TILE_F, TILE_B, mb0);
        bulk_ld(smbase + 3 * TILE_B, vc + (size_t)u * TILE_F, TILE_B, mb0);
    }

    // local metadata tables (4 KB inverse page table + pos + update page)
    for (int i = t; i < NPAGES; i += 512) sinv[pt[i]] = i;
    if (t < NB) {
        int p = pos_[t];
        spos[t] = p;
        supd[t] = pt[t * NPG + (p >> 7)];
    }
    __syncthreads();

    int it = 0;
    for (; u < NUNITS; u += grid, ++it) {
        const int s = it % 3;
        float* kb = smf + s * TILE_F;
        float* vb = smf + (3 + s) * TILE_F;

        __syncthreads();   // prev iter's reads of all buffers done

        // ---- prefetch next unit (stage s+1; its store group is >=2 old) ----
        const int un = u + grid;
        if (t == 0 && un < NUNITS) {
            const int sn = (s + 1) % 3;
            asm volatile("cp.async.bulk.wait_group.read 1;" ::: "memory");
            mbar_expect(mb0 + 8 * sn, 2 * TILE_B);
            bulk_ld(smbase + sn * TILE_B,       kc + (size_t)un * TILE_F, TILE_B, mb0 + 8 * sn);
            bulk_ld(smbase + (3 + sn) * TILE_B, vc + (size_t)un * TILE_F, TILE_B, mb0 + 8 * sn);
        }

        // ---- unit metadata (SMEM tables) ----
        const int pp = u >> 4, h = (u >> 1) & 7, hf = u & 1;
        const int owner = sinv[pp];
        const int b = owner >> 5, lp = owner & 31;
        const int pos = spos[b];
        const int startrow = lp * PS + hf * 64;
        const bool do_attn = startrow <= pos;
        const int nvalid = min(64, pos - startrow + 1);
        const int slot = pos & 127;
        const bool has_upd = (pp == supd[b]) && ((slot >> 6) == hf);
        const size_t base = (size_t)u * TILE_F;

        // ---- wait current tiles ----
        mbar_wait(mb0 + 8 * s, (it / 3) & 1);

        // q load + new-token patch into SMEM (pre-store & pre-compute)
        if (do_attn) qs[t] = q[((size_t)b * NH + h * NG) * ND + t];
        if (has_upd) {
            const int r = slot & 63;
            if (t < 32)
                ((float4*)(kb + r * ND))[t] =
                    ((const float4*)(knew + ((size_t)b * NHKV + h) * ND))[t];
            else if (t < 64)
                ((float4*)(vb + r * ND))[t - 32] =
                    ((const float4*)(vnew + ((size_t)b * NHKV + h) * ND))[t - 32];
        }
        __syncthreads();

        // ---- async bulk store of (patched) tiles ----
        if (t == 0) {
            asm volatile("fence.proxy.async.shared::cta;" ::: "memory");
            bulk_st(ok + base, smbase + s * TILE_B,       TILE_B);
            bulk_st(ov + base, smbase + (3 + s) * TILE_B, TILE_B);
            asm volatile("cp.async.bulk.commit_group;" ::: "memory");
        }

        if (do_attn) {
            // ---- QK: warp w rows {w, w+16, w+32, w+48}; float4 + shuffle ----
            const float4 q0 = ((const float4*)qs)[lane];
            const float4 q1 = ((const float4*)qs)[32 + lane];
            const float4 q2 = ((const float4*)qs)[64 + lane];
            const float4 q3 = ((const float4*)qs)[96 + lane];
            for (int r = w; r < 64; r += 16) {
                float4 kv = ((const float4*)(kb + r * ND))[lane];
                float s0 = kv.x*q0.x + kv.y*q0.y + kv.z*q0.z + kv.w*q0.w;
                float s1 = kv.x*q1.x + kv.y*q1.y + kv.z*q1.z + kv.w*q1.w;
                float s2 = kv.x*q2.x + kv.y*q2.y + kv.z*q2.z + kv.w*q2.w;
                float s3 = kv.x*q3.x + kv.y*q3.y + kv.z*q3.z + kv.w*q3.w;
#pragma unroll
                for (int off = 16; off; off >>= 1) {
                    s0 += __shfl_xor_sync(0xffffffffu, s0, off);
                    s1 += __shfl_xor_sync(0xffffffffu, s1, off);
                    s2 += __shfl_xor_sync(0xffffffffu, s2, off);
                    s3 += __shfl_xor_sync(0xffffffffu, s3, off);
                }
                if (lane == 0) {
                    bool val = r < nvalid;
                    sp[r]       = val ? s0 * SCALE : -INFINITY;
                    sp[64 + r]  = val ? s1 * SCALE : -INFINITY;
                    sp[128 + r] = val ? s2 * SCALE : -INFINITY;
                    sp[192 + r] = val ? s3 * SCALE : -INFINITY;
                }
            }
            __syncthreads();

            // ---- partial softmax: warp g reduces its 64 scores ----
            if (w < NG) {
                float2 v2 = ((const float2*)(sp + w * 64))[lane];
                float m = fmaxf(v2.x, v2.y);
#pragma unroll
                for (int off = 16; off; off >>= 1)
                    m = fmaxf(m, __shfl_xor_sync(0xffffffffu, m, off));
                float ex = __expf(v2.x - m), ey = __expf(v2.y - m);
                float l = ex + ey;
#pragma unroll
                for (int off = 16; off; off >>= 1)
                    l += __shfl_xor_sync(0xffffffffu, l, off);
                ((float2*)(sp + w * 64))[lane] = make_float2(ex, ey);
                if (lane == 0) {
                    int id = (b * NH + h * NG + w) * NHP + lp * 2 + hf;
                    g_Pm[id] = m;
                    g_Pl[id] = l;
                }
            }
            __syncthreads();

            // ---- P*V: thread t -> (qh = t>>7, d = t&127), dual accumulators ----
            const int qh = t >> 7, d = t & 127;
            const float* spq = sp + qh * 64;
            float a0 = 0.f, a1 = 0.f;
            int r = 0;
            for (; r + 1 < nvalid; r += 2) {
                a0 = fmaf(spq[r],     vb[r * ND + d],       a0);
                a1 = fmaf(spq[r + 1], vb[(r + 1) * ND + d], a1);
            }
            if (r < nvalid) a0 = fmaf(spq[r], vb[r * ND + d], a0);
            g_Pacc[(size_t)((b * NH + h * NG + qh) * NHP + lp * 2 + hf) * ND + d] = a0 + a1;
        }
    }

    // drain outstanding bulk stores (SMEM safety + GMEM visibility)
    if (t == 0) asm volatile("cp.async.bulk.wait_group 0;" ::: "memory");
}

// ---------------------------------------------------------------------------
// Parallel split-softmax combine. One block per (b, q-head), 128 threads.
// Phase 1: all (m,l) partials loaded/exp'd IN PARALLEL (one per thread) ->
// coefficients in SMEM. Phase 2: pure unrolled fmaf stream over g_Pacc
// (contiguous 32 KB per block, independent loads).
__global__ void __launch_bounds__(128, 8)
reduce_kernel(const int* __restrict__ pos_, float* __restrict__ out)
{
    __shared__ float sc[NHP];      // coefficients c[hp]
    __shared__ float red[8];       // cross-warp scratch (max / sum)

    const int uu = blockIdx.x;     // b*32 + h*4 + g
    const int b = uu >> 5;
    const int t = threadIdx.x;
    const int w = t >> 5, lane = t & 31;
    const int nhp = (pos_[b] >> 6) + 1;   // 1..64 valid partials

    // ---- phase 1: parallel coefficients ----
    float m = -INFINITY, l = 0.f;
    if (t < nhp) { m = g_Pm[uu * NHP + t]; l = g_Pl[uu * NHP + t]; }

    // block max over 128 threads (threads >= nhp contribute -inf)
    float M = m;
#pragma unroll
    for (int off = 16; off; off >>= 1)
        M = fmaxf(M, __shfl_xor_sync(0xffffffffu, M, off));
    if (lane == 0) red[w] = M;
    __syncthreads();
    M = fmaxf(fmaxf(red[0], red[1]), fmaxf(red[2], red[3]));

    const float c = (t < nhp) ? __expf(m - M) : 0.f;
    if (t < NHP) sc[t] = c;

    // L = sum c*l (block reduction)
    float cl = c * l;
#pragma unroll
    for (int off = 16; off; off >>= 1)
        cl += __shfl_xor_sync(0xffffffffu, cl, off);
    if (lane == 0) red[4 + w] = cl;
    __syncthreads();
    const float L = red[4] + red[5] + red[6] + red[7];

    // ---- phase 2: O[d] = sum_hp c[hp] * Pacc[hp][d] ; d = t ----
    const float* pa = g_Pacc + (size_t)uu * NHP * ND + t;
    float O = 0.f;
    int hp = 0;
#pragma unroll 4
    for (; hp + 3 < nhp; hp += 4) {
        float v0 = pa[(size_t)hp * ND];
        float v1 = pa[(size_t)(hp + 1) * ND];
        float v2 = pa[(size_t)(hp + 2) * ND];
        float v3 = pa[(size_t)(hp + 3) * ND];
        O = fmaf(v0, sc[hp],     O);
        O = fmaf(v1, sc[hp + 1], O);
        O = fmaf(v2, sc[hp + 2], O);
        O = fmaf(v3, sc[hp + 3], O);
    }
    for (; hp < nhp; hp++)
        O = fmaf(pa[(size_t)hp * ND], sc[hp], O);

    out[(size_t)uu * ND + t] = O / L;
}

// ---------------------------------------------------------------------------
extern "C" void kernel_launch(void* const* d_in, const int* in_sizes, int n_in,
                              void* d_out, int out_size)
{
    const float* q   = (const float*)d_in[0];
    const float* kn  = (const float*)d_in[1];
    const float* vn  = (const float*)d_in[2];
    const float* kc  = (const float*)d_in[3];
    const float* vc  = (const float*)d_in[4];
    const int*   pos = (const int*)d_in[5];
    const int*   pt  = (const int*)d_in[6];

    float* out_attn = (float*)d_out;
    float* out_k    = out_attn + (size_t)NB * NH * ND;             // +131072
    float* out_v    = out_k + (size_t)NPAGES * NHKV * PS * ND;     // +134217728

    int nsm = 148;
    if (cudaDeviceGetAttribute(&nsm, cudaDevAttrMultiProcessorCount, 0) != cudaSuccess || nsm <= 0)
        nsm = 148;

    // 6 tiles*32KB + qs 2KB + sp 1KB + mbars 64B + sinv 4KB + spos/supd 256B
    const int smem = (6 * TILE_F + 512 + 256 + 16 + 1024 + 64) * (int)sizeof(float); // 204128 B
    cudaFuncSetAttribute(fused_kernel, cudaFuncAttributeMaxDynamicSharedMemorySize, smem);

    fused_kernel<<<nsm, 512, smem>>>(q, kn, vn, kc, vc, pos, pt, out_k, out_v);
    reduce_kernel<<<NB * NH, 128>>>(pos, out_attn);
}

// round 15
// speedup vs baseline: 1.1464x; 1.0064x over previous
#include <cuda_runtime.h>
#include <cstdint>
#include <math.h>

#define NB     32
#define NH     32
#define NHKV   8
#define NG     4
#define ND     128
#define NPG    32
#define PS     128
#define NPAGES 1024
#define NUNITS (NPAGES * NHKV * 2)     // 16384 half-page units, physical order
#define NHP    64                      // partials per (b,qhead): lp*2+hf
#define TILE_F 8192                    // floats per half tile (64 x 128)
#define TILE_B 32768u
#define SCALE  0.08838834764831845f    // 1/sqrt(128)

// -------- device scratch (static: allocation-free) --------
__device__ float g_Pm[NB * NH * NHP];                           // partial max
__device__ float g_Pl[NB * NH * NHP];                           // partial expsum
__device__ float g_Pacc[(size_t)NB * NH * NHP * ND];            // partial P*V (33.5 MB)

// ---------------- PTX helpers ----------------
__device__ __forceinline__ void mbar_init(uint32_t a, int cnt) {
    asm volatile("mbarrier.init.shared.b64 [%0], %1;" :: "r"(a), "r"(cnt) : "memory");
}
__device__ __forceinline__ void mbar_expect(uint32_t a, uint32_t bytes) {
    asm volatile("mbarrier.arrive.expect_tx.shared.b64 _, [%0], %1;"
                 :: "r"(a), "r"(bytes) : "memory");
}
__device__ __forceinline__ void mbar_wait(uint32_t a, int parity) {
    asm volatile(
        "{\n\t.reg .pred P;\n\t"
        "W%=:\n\t"
        "mbarrier.try_wait.parity.acquire.cta.shared::cta.b64 P, [%0], %1, 0x989680;\n\t"
        "@P bra.uni D%=;\n\t"
        "bra.uni W%=;\n\t"
        "D%=:\n\t}"
        :: "r"(a), "r"(parity) : "memory");
}
__device__ __forceinline__ void bulk_ld(uint32_t dst, const void* src, uint32_t bytes, uint32_t mbar) {
    asm volatile("cp.async.bulk.shared::cta.global.mbarrier::complete_tx::bytes [%0], [%1], %2, [%3];"
                 :: "r"(dst), "l"(src), "r"(bytes), "r"(mbar) : "memory");
}
__device__ __forceinline__ void bulk_st(void* dst, uint32_t src, uint32_t bytes) {
    asm volatile("cp.async.bulk.global.shared::cta.bulk_group [%0], [%1], %2;"
                 :: "l"(dst), "r"(src), "r"(bytes) : "memory");
}

// ---------------------------------------------------------------------------
// Persistent fused update+copy+attend (R9's proven 336us hot loop, verbatim:
// strided physical-order units, 64KB steps, per-unit split-softmax partials).
__global__ void __launch_bounds__(512, 1)
fused_kernel(const float* __restrict__ q,
             const float* __restrict__ knew,
             const float* __restrict__ vnew,
             const float* __restrict__ kc,
             const float* __restrict__ vc,
             const int*   __restrict__ pos_,
             const int*   __restrict__ pt,
             float* __restrict__ ok,
             float* __restrict__ ov)
{
    extern __shared__ __align__(128) float smf[];
    // layout: K tiles [3][8192] | V tiles [3][8192] | qs[512] | sp[256] |
    //         mbars(16f) | sinv[1024] | spos[32] | supd[32]
    float* qs = smf + 6 * TILE_F;
    float* sp = qs + 512;
    const uint32_t smbase = (uint32_t)__cvta_generic_to_shared(smf);
    const uint32_t mb0 = (uint32_t)__cvta_generic_to_shared(sp + 256);
    int*  sinv = (int*)(sp + 256 + 16);
    int*  spos = sinv + 1024;
    int*  supd = spos + 32;

    const int t = threadIdx.x;
    const int w = t >> 5, lane = t & 31;
    const int grid = gridDim.x;

    if (t == 0) {
#pragma unroll
        for (int i = 0; i < 3; i++) mbar_init(mb0 + 8 * i, 1);
    }

    int u = blockIdx.x;
    // prologue prefetch (pure physical address, needs no metadata)
    if (t == 0 && u < NUNITS) {
        mbar_expect(mb0, 2 * TILE_B);
        bulk_ld(smbase,              kc + (size_t)u * TILE_F, TILE_B, mb0);
        bulk_ld(smbase + 3 * TILE_B, vc + (size_t)u * TILE_F, TILE_B, mb0);
    }

    // local metadata tables (4 KB inverse page table + pos + update page)
    for (int i = t; i < NPAGES; i += 512) sinv[pt[i]] = i;
    if (t < NB) {
        int p = pos_[t];
        spos[t] = p;
        supd[t] = pt[t * NPG + (p >> 7)];
    }
    __syncthreads();

    int it = 0;
    for (; u < NUNITS; u += grid, ++it) {
        const int s = it % 3;
        float* kb = smf + s * TILE_F;
        float* vb = smf + (3 + s) * TILE_F;

        __syncthreads();   // prev iter's reads of all buffers done

        // ---- prefetch next unit (stage s+1; its store group is >=2 old) ----
        const int un = u + grid;
        if (t == 0 && un < NUNITS) {
            const int sn = (s + 1) % 3;
            asm volatile("cp.async.bulk.wait_group.read 1;" ::: "memory");
            mbar_expect(mb0 + 8 * sn, 2 * TILE_B);
            bulk_ld(smbase + sn * TILE_B,       kc + (size_t)un * TILE_F, TILE_B, mb0 + 8 * sn);
            bulk_ld(smbase + (3 + sn) * TILE_B, vc + (size_t)un * TILE_F, TILE_B, mb0 + 8 * sn);
        }

        // ---- unit metadata (SMEM tables) ----
        const int pp = u >> 4, h = (u >> 1) & 7, hf = u & 1;
        const int owner = sinv[pp];
        const int b = owner >> 5, lp = owner & 31;
        const int pos = spos[b];
        const int startrow = lp * PS + hf * 64;
        const bool do_attn = startrow <= pos;
        const int nvalid = min(64, pos - startrow + 1);
        const int slot = pos & 127;
        const bool has_upd = (pp == supd[b]) && ((slot >> 6) == hf);
        const size_t base = (size_t)u * TILE_F;

        // ---- wait current tiles ----
        mbar_wait(mb0 + 8 * s, (it / 3) & 1);

        // q load + new-token patch into SMEM (pre-store & pre-compute)
        if (do_attn) qs[t] = q[((size_t)b * NH + h * NG) * ND + t];
        if (has_upd) {
            const int r = slot & 63;
            if (t < 32)
                ((float4*)(kb + r * ND))[t] =
                    ((const float4*)(knew + ((size_t)b * NHKV + h) * ND))[t];
            else if (t < 64)
                ((float4*)(vb + r * ND))[t - 32] =
                    ((const float4*)(vnew + ((size_t)b * NHKV + h) * ND))[t - 32];
        }
        __syncthreads();

        // ---- async bulk store of (patched) tiles ----
        if (t == 0) {
            asm volatile("fence.proxy.async.shared::cta;" ::: "memory");
            bulk_st(ok + base, smbase + s * TILE_B,       TILE_B);
            bulk_st(ov + base, smbase + (3 + s) * TILE_B, TILE_B);
            asm volatile("cp.async.bulk.commit_group;" ::: "memory");
        }

        if (do_attn) {
            // ---- QK: warp w rows {w, w+16, w+32, w+48}; float4 + shuffle ----
            const float4 q0 = ((const float4*)qs)[lane];
            const float4 q1 = ((const float4*)qs)[32 + lane];
            const float4 q2 = ((const float4*)qs)[64 + lane];
            const float4 q3 = ((const float4*)qs)[96 + lane];
            for (int r = w; r < 64; r += 16) {
                float4 kv = ((const float4*)(kb + r * ND))[lane];
                float s0 = kv.x*q0.x + kv.y*q0.y + kv.z*q0.z + kv.w*q0.w;
                float s1 = kv.x*q1.x + kv.y*q1.y + kv.z*q1.z + kv.w*q1.w;
                float s2 = kv.x*q2.x + kv.y*q2.y + kv.z*q2.z + kv.w*q2.w;
                float s3 = kv.x*q3.x + kv.y*q3.y + kv.z*q3.z + kv.w*q3.w;
#pragma unroll
                for (int off = 16; off; off >>= 1) {
                    s0 += __shfl_xor_sync(0xffffffffu, s0, off);
                    s1 += __shfl_xor_sync(0xffffffffu, s1, off);
                    s2 += __shfl_xor_sync(0xffffffffu, s2, off);
                    s3 += __shfl_xor_sync(0xffffffffu, s3, off);
                }
                if (lane == 0) {
                    bool val = r < nvalid;
                    sp[r]       = val ? s0 * SCALE : -INFINITY;
                    sp[64 + r]  = val ? s1 * SCALE : -INFINITY;
                    sp[128 + r] = val ? s2 * SCALE : -INFINITY;
                    sp[192 + r] = val ? s3 * SCALE : -INFINITY;
                }
            }
            __syncthreads();

            // ---- partial softmax: warp g reduces its 64 scores ----
            if (w < NG) {
                float2 v2 = ((const float2*)(sp + w * 64))[lane];
                float m = fmaxf(v2.x, v2.y);
#pragma unroll
                for (int off = 16; off; off >>= 1)
                    m = fmaxf(m, __shfl_xor_sync(0xffffffffu, m, off));
                float ex = __expf(v2.x - m), ey = __expf(v2.y - m);
                float l = ex + ey;
#pragma unroll
                for (int off = 16; off; off >>= 1)
                    l += __shfl_xor_sync(0xffffffffu, l, off);
                ((float2*)(sp + w * 64))[lane] = make_float2(ex, ey);
                if (lane == 0) {
                    int id = (b * NH + h * NG + w) * NHP + lp * 2 + hf;
                    g_Pm[id] = m;
                    g_Pl[id] = l;
                }
            }
            __syncthreads();

            // ---- P*V: thread t -> (qh = t>>7, d = t&127), dual accumulators ----
            const int qh = t >> 7, d = t & 127;
            const float* spq = sp + qh * 64;
            float a0 = 0.f, a1 = 0.f;
            int r = 0;
            for (; r + 1 < nvalid; r += 2) {
                a0 = fmaf(spq[r],     vb[r * ND + d],       a0);
                a1 = fmaf(spq[r + 1], vb[(r + 1) * ND + d], a1);
            }
            if (r < nvalid) a0 = fmaf(spq[r], vb[r * ND + d], a0);
            g_Pacc[(size_t)((b * NH + h * NG + qh) * NHP + lp * 2 + hf) * ND + d] = a0 + a1;
        }
    }

    // drain outstanding bulk stores (SMEM safety + GMEM visibility)
    if (t == 0) asm volatile("cp.async.bulk.wait_group 0;" ::: "memory");
}

// ---------------------------------------------------------------------------
// Parallel split-softmax combine. One block per (b, q-head), 128 threads.
// Phase 1: all (m,l) partials loaded/exp'd IN PARALLEL (one per thread) ->
// coefficients in SMEM. Phase 2: pure unrolled fmaf stream over g_Pacc
// (contiguous 32 KB per block, independent loads).
__global__ void __launch_bounds__(128, 8)
reduce_kernel(const int* __restrict__ pos_, float* __restrict__ out)
{
    __shared__ float sc[NHP];      // coefficients c[hp]
    __shared__ float red[8];       // cross-warp scratch (max / sum)

    const int uu = blockIdx.x;     // b*32 + h*4 + g
    const int b = uu >> 5;
    const int t = threadIdx.x;
    const int w = t >> 5, lane = t & 31;
    const int nhp = (pos_[b] >> 6) + 1;   // 1..64 valid partials

    // ---- phase 1: parallel coefficients ----
    float m = -INFINITY, l = 0.f;
    if (t < nhp) { m = g_Pm[uu * NHP + t]; l = g_Pl[uu * NHP + t]; }

    // block max over 128 threads (threads >= nhp contribute -inf)
    float M = m;
#pragma unroll
    for (int off = 16; off; off >>= 1)
        M = fmaxf(M, __shfl_xor_sync(0xffffffffu, M, off));
    if (lane == 0) red[w] = M;
    __syncthreads();
    M = fmaxf(fmaxf(red[0], red[1]), fmaxf(red[2], red[3]));

    const float c = (t < nhp) ? __expf(m - M) : 0.f;
    if (t < NHP) sc[t] = c;

    // L = sum c*l (block reduction)
    float cl = c * l;
#pragma unroll
    for (int off = 16; off; off >>= 1)
        cl += __shfl_xor_sync(0xffffffffu, cl, off);
    if (lane == 0) red[4 + w] = cl;
    __syncthreads();
    const float L = red[4] + red[5] + red[6] + red[7];

    // ---- phase 2: O[d] = sum_hp c[hp] * Pacc[hp][d] ; d = t ----
    const float* pa = g_Pacc + (size_t)uu * NHP * ND + t;
    float O = 0.f;
    int hp = 0;
#pragma unroll 4
    for (; hp + 3 < nhp; hp += 4) {
        float v0 = pa[(size_t)hp * ND];
        float v1 = pa[(size_t)(hp + 1) * ND];
        float v2 = pa[(size_t)(hp + 2) * ND];
        float v3 = pa[(size_t)(hp + 3) * ND];
        O = fmaf(v0, sc[hp],     O);
        O = fmaf(v1, sc[hp + 1], O);
        O = fmaf(v2, sc[hp + 2], O);
        O = fmaf(v3, sc[hp + 3], O);
    }
    for (; hp < nhp; hp++)
        O = fmaf(pa[(size_t)hp * ND], sc[hp], O);

    out[(size_t)uu * ND + t] = O / L;
}

// ---------------------------------------------------------------------------
extern "C" void kernel_launch(void* const* d_in, const int* in_sizes, int n_in,
                              void* d_out, int out_size)
{
    const float* q   = (const float*)d_in[0];
    const float* kn  = (const float*)d_in[1];
    const float* vn  = (const float*)d_in[2];
    const float* kc  = (const float*)d_in[3];
    const float* vc  = (const float*)d_in[4];
    const int*   pos = (const int*)d_in[5];
    const int*   pt  = (const int*)d_in[6];

    float* out_attn = (float*)d_out;
    float* out_k    = out_attn + (size_t)NB * NH * ND;             // +131072
    float* out_v    = out_k + (size_t)NPAGES * NHKV * PS * ND;     // +134217728

    int nsm = 148;
    if (cudaDeviceGetAttribute(&nsm, cudaDevAttrMultiProcessorCount, 0) != cudaSuccess || nsm <= 0)
        nsm = 148;

    // 6 tiles*32KB + qs 2KB + sp 1KB + mbars 64B + sinv 4KB + spos/supd 256B
    const int smem = (6 * TILE_F + 512 + 256 + 16 + 1024 + 64) * (int)sizeof(float); // 204128 B
    cudaFuncSetAttribute(fused_kernel, cudaFuncAttributeMaxDynamicSharedMemorySize, smem);

    fused_kernel<<<nsm, 512, smem>>>(q, kn, vn, kc, vc, pos, pt, out_k, out_v);
    reduce_kernel<<<NB * NH, 128>>>(pos, out_attn);
}